// round 1
// baseline (speedup 1.0000x reference)
#include <cuda_runtime.h>
#include <math.h>

#define BATCH   2
#define SEQ     1024
#define DMODEL  1024
#define DINNER  2048
#define DTRANK  64
#define DSTATE  16
#define DCONV   4
#define ROWS    (BATCH*SEQ)            // 2048
#define XPROJ_OUT (DTRANK + 2*DSTATE)  // 96

// ---------------- scratch (static device globals; no allocation) ------------
__device__ float g_xn   [ROWS*DMODEL];
__device__ float g_xz   [ROWS*2*DINNER];
__device__ float g_u    [ROWS*DINNER];
__device__ float g_xdbl [ROWS*XPROJ_OUT];
__device__ float g_delta[ROWS*DINNER];
__device__ float g_y    [ROWS*DINNER];
__device__ float g_yg   [ROWS*DINNER];

// ---------------- LayerNorm: one block per row ------------------------------
__global__ void ln_kernel(const float* __restrict__ x, const float* __restrict__ g,
                          const float* __restrict__ b, float* __restrict__ out)
{
    int row = blockIdx.x;
    int tid = threadIdx.x;
    const float* xr = x + (size_t)row*DMODEL;
    float v[4];
    float s1 = 0.f, s2 = 0.f;
    #pragma unroll
    for (int i = 0; i < 4; i++) {
        v[i] = xr[tid + 256*i];
        s1 += v[i];
        s2 += v[i]*v[i];
    }
    __shared__ float sh1[8], sh2[8];
    #pragma unroll
    for (int o = 16; o; o >>= 1) {
        s1 += __shfl_xor_sync(0xffffffffu, s1, o);
        s2 += __shfl_xor_sync(0xffffffffu, s2, o);
    }
    if ((tid & 31) == 0) { sh1[tid>>5] = s1; sh2[tid>>5] = s2; }
    __syncthreads();
    if (tid < 32) {
        float a = (tid < 8) ? sh1[tid] : 0.f;
        float c = (tid < 8) ? sh2[tid] : 0.f;
        #pragma unroll
        for (int o = 4; o; o >>= 1) {
            a += __shfl_xor_sync(0xffffffffu, a, o);
            c += __shfl_xor_sync(0xffffffffu, c, o);
        }
        if (tid == 0) { sh1[0] = a; sh2[0] = c; }
    }
    __syncthreads();
    float mu  = sh1[0] * (1.f/DMODEL);
    float var = sh2[0] * (1.f/DMODEL) - mu*mu;
    float r   = rsqrtf(var + 1e-5f);
    float* o = out + (size_t)row*DMODEL;
    #pragma unroll
    for (int i = 0; i < 4; i++) {
        int c = tid + 256*i;
        o[c] = (v[i]-mu)*r*g[c] + b[c];
    }
}

// ---------------- SGEMM NT: C[M,N] = A[M,K] * B[N,K]^T (+ optional R) -------
// 128x128 block tile, BK=8, 256 threads, 8x8 per-thread (split 4+4).
#define BM 128
#define BN 128
#define BKT 8

__global__ __launch_bounds__(256) void sgemm_nt(
    const float* __restrict__ A, int lda,
    const float* __restrict__ B, int ldb,
    float* __restrict__ C, int ldc,
    const float* __restrict__ R, int ldr,
    int M, int N, int K)
{
    __shared__ float As[BKT][BM+4];
    __shared__ float Bs[BKT][BN+4];

    int tid = threadIdx.x;
    int tx  = tid & 15;   // 0..15
    int ty  = tid >> 4;   // 0..15
    int m0  = blockIdx.y * BM;
    int n0  = blockIdx.x * BN;

    int lrow = tid >> 1;         // 0..127
    int lk4  = (tid & 1) * 4;    // 0 / 4

    float acc[8][8];
    #pragma unroll
    for (int i = 0; i < 8; i++)
        #pragma unroll
        for (int j = 0; j < 8; j++) acc[i][j] = 0.f;

    for (int k0 = 0; k0 < K; k0 += BKT) {
        float4 a = make_float4(0.f,0.f,0.f,0.f);
        int am = m0 + lrow;
        if (am < M) a = *reinterpret_cast<const float4*>(A + (size_t)am*lda + k0 + lk4);
        As[lk4+0][lrow] = a.x; As[lk4+1][lrow] = a.y;
        As[lk4+2][lrow] = a.z; As[lk4+3][lrow] = a.w;

        float4 bv = make_float4(0.f,0.f,0.f,0.f);
        int bn = n0 + lrow;
        if (bn < N) bv = *reinterpret_cast<const float4*>(B + (size_t)bn*ldb + k0 + lk4);
        Bs[lk4+0][lrow] = bv.x; Bs[lk4+1][lrow] = bv.y;
        Bs[lk4+2][lrow] = bv.z; Bs[lk4+3][lrow] = bv.w;

        __syncthreads();

        #pragma unroll
        for (int kk = 0; kk < BKT; kk++) {
            float ra[8], rb[8];
            #pragma unroll
            for (int i = 0; i < 4; i++) {
                ra[i]   = As[kk][ty*4 + i];
                ra[i+4] = As[kk][64 + ty*4 + i];
                rb[i]   = Bs[kk][tx*4 + i];
                rb[i+4] = Bs[kk][64 + tx*4 + i];
            }
            #pragma unroll
            for (int i = 0; i < 8; i++)
                #pragma unroll
                for (int j = 0; j < 8; j++)
                    acc[i][j] = fmaf(ra[i], rb[j], acc[i][j]);
        }
        __syncthreads();
    }

    #pragma unroll
    for (int i = 0; i < 8; i++) {
        int m = m0 + ((i < 4) ? (ty*4 + i) : (64 + ty*4 + i - 4));
        if (m >= M) continue;
        #pragma unroll
        for (int j = 0; j < 8; j++) {
            int n = n0 + ((j < 4) ? (tx*4 + j) : (64 + tx*4 + j - 4));
            if (n < N) {
                float val = acc[i][j];
                if (R) val += R[(size_t)m*ldr + n];
                C[(size_t)m*ldc + n] = val;
            }
        }
    }
}

// ---------------- causal depthwise conv1d + SiLU ----------------------------
__global__ void conv_silu_kernel(const float* __restrict__ xz, const float* __restrict__ w,
                                 const float* __restrict__ bias, float* __restrict__ u)
{
    int i = blockIdx.x*blockDim.x + threadIdx.x;
    if (i >= ROWS*DINNER) return;
    int d    = i % DINNER;
    int row  = i / DINNER;       // b*SEQ + l
    int l    = row % SEQ;
    float acc = bias[d];
    #pragma unroll
    for (int t = 0; t < DCONV; t++) {
        int li = l + t - (DCONV-1);
        if (li >= 0)
            acc += xz[((size_t)(row + li - l))*(2*DINNER) + d] * w[d*DCONV + t];
    }
    float sig = 1.f / (1.f + expf(-acc));
    u[i] = acc * sig;
}

// ---------------- softplus(delta_raw + bias) --------------------------------
__global__ void softplus_kernel(float* __restrict__ delta, const float* __restrict__ bias)
{
    int i = blockIdx.x*blockDim.x + threadIdx.x;
    if (i >= ROWS*DINNER) return;
    float v = delta[i] + bias[i % DINNER];
    delta[i] = (v > 20.f) ? v : log1pf(expf(v));
}

// ---------------- selective scan: 1 lane per (channel,state) ----------------
// 2 channels per warp (16 lanes each), h in register, shfl-reduce for y.
__global__ __launch_bounds__(256) void scan_kernel(
    const float* __restrict__ delta, const float* __restrict__ u,
    const float* __restrict__ xdbl, const float* __restrict__ A_log,
    const float* __restrict__ Dskip, float* __restrict__ y)
{
    int warp = threadIdx.x >> 5;
    int lane = threadIdx.x & 31;
    int half = lane >> 4;
    int n    = lane & 15;
    int c    = blockIdx.x*16 + warp*2 + half;   // 0..4095
    int b    = c / DINNER;
    int d    = c % DINNER;

    float A  = -expf(A_log[d*DSTATE + n]);
    float Dd = Dskip[d];
    float h  = 0.f;

    const float* drow = delta + (size_t)b*SEQ*DINNER + d;
    const float* urow = u     + (size_t)b*SEQ*DINNER + d;
    const float* xrow = xdbl  + (size_t)b*SEQ*XPROJ_OUT;
    float*       yrow = y     + (size_t)b*SEQ*DINNER + d;

    for (int t = 0; t < SEQ; t++) {
        float dt = drow[(size_t)t*DINNER];
        float ut = urow[(size_t)t*DINNER];
        float Bn = xrow[t*XPROJ_OUT + DTRANK + n];
        float Cn = xrow[t*XPROJ_OUT + DTRANK + DSTATE + n];
        float dA = expf(dt * A);
        h = fmaf(dA, h, dt*ut*Bn);
        float p = h * Cn;
        p += __shfl_xor_sync(0xffffffffu, p, 8);
        p += __shfl_xor_sync(0xffffffffu, p, 4);
        p += __shfl_xor_sync(0xffffffffu, p, 2);
        p += __shfl_xor_sync(0xffffffffu, p, 1);
        if (n == 0) yrow[(size_t)t*DINNER] = fmaf(ut, Dd, p);
    }
}

// ---------------- gate: yg = y * silu(z) ------------------------------------
__global__ void gate_kernel(const float* __restrict__ y, const float* __restrict__ xz,
                            float* __restrict__ yg)
{
    int i = blockIdx.x*blockDim.x + threadIdx.x;
    if (i >= ROWS*DINNER) return;
    int d   = i % DINNER;
    int row = i / DINNER;
    float z = xz[(size_t)row*2*DINNER + DINNER + d];
    float s = z / (1.f + expf(-z));
    yg[i] = y[i] * s;
}

// ---------------- launch ----------------------------------------------------
extern "C" void kernel_launch(void* const* d_in, const int* in_sizes, int n_in,
                              void* d_out, int out_size)
{
    const float* x      = (const float*)d_in[0];
    const float* ln_g   = (const float*)d_in[1];
    const float* ln_b   = (const float*)d_in[2];
    const float* w_in   = (const float*)d_in[3];
    const float* conv_w = (const float*)d_in[4];
    const float* conv_b = (const float*)d_in[5];
    const float* w_x    = (const float*)d_in[6];
    const float* w_dt   = (const float*)d_in[7];
    const float* b_dt   = (const float*)d_in[8];
    const float* A_log  = (const float*)d_in[9];
    const float* Dsk    = (const float*)d_in[10];
    const float* w_out  = (const float*)d_in[11];
    float* out = (float*)d_out;

    float *xn, *xz, *u, *xdbl, *delta, *y, *yg;
    cudaGetSymbolAddress((void**)&xn,    g_xn);
    cudaGetSymbolAddress((void**)&xz,    g_xz);
    cudaGetSymbolAddress((void**)&u,     g_u);
    cudaGetSymbolAddress((void**)&xdbl,  g_xdbl);
    cudaGetSymbolAddress((void**)&delta, g_delta);
    cudaGetSymbolAddress((void**)&y,     g_y);
    cudaGetSymbolAddress((void**)&yg,    g_yg);

    int nelem = ROWS*DINNER;

    // 1. layernorm
    ln_kernel<<<ROWS, 256>>>(x, ln_g, ln_b, xn);

    // 2. in_proj: xz[2048,4096] = xn[2048,1024] @ w_in[4096,1024]^T
    {
        dim3 g(2*DINNER/BN, ROWS/BM);
        sgemm_nt<<<g, 256>>>(xn, DMODEL, w_in, DMODEL, xz, 2*DINNER,
                             nullptr, 0, ROWS, 2*DINNER, DMODEL);
    }

    // 3. causal depthwise conv + SiLU -> u
    conv_silu_kernel<<<(nelem+255)/256, 256>>>(xz, conv_w, conv_b, u);

    // 4. x_proj: xdbl[2048,96] = u @ w_x[96,2048]^T
    {
        dim3 g(1, ROWS/BM);
        sgemm_nt<<<g, 256>>>(u, DINNER, w_x, DINNER, xdbl, XPROJ_OUT,
                             nullptr, 0, ROWS, XPROJ_OUT, DINNER);
    }

    // 5. dt_proj: delta_raw[2048,2048] = xdbl[:, :64] @ w_dt[2048,64]^T
    {
        dim3 g(DINNER/BN, ROWS/BM);
        sgemm_nt<<<g, 256>>>(xdbl, XPROJ_OUT, w_dt, DTRANK, delta, DINNER,
                             nullptr, 0, ROWS, DINNER, DTRANK);
    }

    // 6. softplus(+bias)
    softplus_kernel<<<(nelem+255)/256, 256>>>(delta, b_dt);

    // 7. selective scan (+ u*D_skip)
    scan_kernel<<<(BATCH*DINNER)/16, 256>>>(delta, u, xdbl, A_log, Dsk, y);

    // 8. gate with silu(z)
    gate_kernel<<<(nelem+255)/256, 256>>>(y, xz, yg);

    // 9. out_proj + residual
    {
        dim3 g(DMODEL/BN, ROWS/BM);
        sgemm_nt<<<g, 256>>>(yg, DINNER, w_out, DINNER, out, DMODEL,
                             x, DMODEL, ROWS, DMODEL, DINNER);
    }
}